// round 11
// baseline (speedup 1.0000x reference)
#include <cuda_runtime.h>
#include <cuda_fp16.h>
#include <cstdint>

// ===================== problem constants =====================
// x: 262144 rows x 128; W: (8,128,128); b: (8,128)
// CTA job: 64 rows (M) x 128 cols (N) x K=128. Channel constant per 4 jobs.
#define N_DIM      128
#define K_DIM      128
#define ROWS_JOB   64
#define THREADS    256
#define NUM_CTAS   4096
#define K_CHUNK    32
#define NCHUNK     4

// ---- smem layout (32-bit words) ----
// [W fp16 frag image: 8192 words][A fp16 2 bufs: 2 x 64 x 20 words][bias 128]
#define OFF_W        0
#define W_IMG_WORDS  8192
#define F16_ROW_W    20                       // words per A row (40 halves) -> LDSM conflict-free
#define F16_BUF_WORDS (ROWS_JOB * F16_ROW_W)  // 1280
#define OFF_A        W_IMG_WORDS              // 8192
#define OFF_BIAS     (OFF_A + 2 * F16_BUF_WORDS)   // 10752
#define SMEM_FLOATS  (OFF_BIAS + 128)
#define SMEM_BYTES   (SMEM_FLOATS * 4)        // 43,520 (x3 CTAs = 130.5KB <= 228KB)

// ===================== helpers =====================
__device__ __forceinline__ uint32_t smem_u32(const void* p) {
    uint32_t a;
    asm("{ .reg .u64 t; cvta.to.shared.u64 t, %1; cvt.u32.u64 %0, t; }" : "=r"(a) : "l"(p));
    return a;
}
__device__ __forceinline__ void cp_async16(uint32_t dst, const void* src) {
    asm volatile("cp.async.cg.shared.global [%0], [%1], 16;" :: "r"(dst), "l"(src));
}
#define CP_COMMIT()  asm volatile("cp.async.commit_group;" ::: "memory")
#define CP_WAIT(n)   asm volatile("cp.async.wait_group %0;" :: "n"(n) : "memory")

__device__ __forceinline__ void ldsm_x4(uint32_t& r0, uint32_t& r1, uint32_t& r2, uint32_t& r3,
                                        uint32_t addr) {
    asm volatile("ldmatrix.sync.aligned.m8n8.x4.shared.b16 {%0,%1,%2,%3}, [%4];"
                 : "=r"(r0), "=r"(r1), "=r"(r2), "=r"(r3) : "r"(addr));
}

// m16n8k16 fp16 MMA, fp32 accumulate
__device__ __forceinline__ void mma_f16(float* c, const uint32_t* a, uint32_t b0, uint32_t b1) {
    asm volatile(
        "mma.sync.aligned.m16n8k16.row.col.f32.f16.f16.f32 "
        "{%0,%1,%2,%3}, {%4,%5,%6,%7}, {%8,%9}, {%0,%1,%2,%3};"
        : "+f"(c[0]), "+f"(c[1]), "+f"(c[2]), "+f"(c[3])
        : "r"(a[0]), "r"(a[1]), "r"(a[2]), "r"(a[3]), "r"(b0), "r"(b1));
}

// ===================== W fp16 fragment image (validated rounds 8-10) =====================
// Per (ch, kc): 4096 halves (512 float4s). fi4 = (p*2+ks)*32+lane holds
// { b0(nt=2p), b1(nt=2p), b0(nt=2p+1), b1(nt=2p+1) } fp16x2 fragments,
// p = 16-col group (0..7), ks = k16 step (0..1) within the 32-k chunk.
__device__ __align__(16) __half g_Wimg[8 * 4 * 4096];

__global__ void prep_w_kernel(const float* __restrict__ W) {
    int idx = blockIdx.x * blockDim.x + threadIdx.x;   // 0 .. 131071
    if (idx >= 8 * 128 * 128) return;
    int ch = idx >> 14;
    int n  = (idx >> 7) & 127;
    int k  = idx & 127;
    int kc = k >> 5;
    int ks = (k >> 4) & 1;
    int bix = (k >> 3) & 1;
    int hsel = k & 1;
    int lane = ((n & 7) << 2) | ((k >> 1) & 3);
    int p = n >> 4;
    int ntodd = (n >> 3) & 1;
    int e = ntodd * 2 + bix;
    int fi4 = (p * 2 + ks) * 32 + lane;
    g_Wimg[(ch * 4 + kc) * 4096 + fi4 * 8 + e * 2 + hsel] = __float2half_rn(W[idx]);
}

// ===================== main GEMM =====================
__global__ __launch_bounds__(THREADS, 3)
void gemm_kernel(const float* __restrict__ x, const float* __restrict__ bias,
                 float* __restrict__ out) {
    extern __shared__ __align__(16) float smem[];
    const uint32_t sm_base = smem_u32(smem);

    const int tid  = threadIdx.x;
    const int lane = tid & 31;
    const int wid  = tid >> 5;
    const int blk  = blockIdx.x;
    const int ch   = (blk >> 2) & 7;      // 256 rows per (b,i) block = 4 jobs of 64

    const float* a_base = x + (size_t)blk * (ROWS_JOB * K_DIM);
    float*       o_base = out + (size_t)blk * (ROWS_JOB * N_DIM);

    // ---- prologue: W image (32KB) via cp.async; bias; A chunk 0 via LDG ----
    {
        const __half* wsrc = g_Wimg + ch * 16384;
        uint32_t sw = sm_base + OFF_W * 4u;
#pragma unroll
        for (int j = 0; j < 8; j++) {
            int pid = j * THREADS + tid;
            cp_async16(sw + (uint32_t)pid * 16u, wsrc + pid * 8);
        }
        CP_COMMIT();
    }
    if (tid < 128) smem[OFF_BIAS + tid] = bias[ch * 128 + tid];

    // 8 warps: 2 over M (32 rows each), 4 over N (32 cols each)
    const int wm = wid >> 2;              // 0..1
    const int wn = wid & 3;               // 0..3
    const int warpM = wm * 32;

    float acc[2][4][4];
#pragma unroll
    for (int mt = 0; mt < 2; mt++)
#pragma unroll
        for (int nt = 0; nt < 4; nt++)
#pragma unroll
            for (int q = 0; q < 4; q++) acc[mt][nt][q] = 0.0f;

    uint32_t* const abufw = (uint32_t*)(smem + OFF_A);

    // per-thread A piece: pid = j*256+tid (j<2) -> row pid>>3 (0..63), col4 pid&7
    const int arow = tid >> 3;            // rows arow, arow+32
    const int apc  = tid & 7;

    // LDG chunk 0
    float4 v[2];
#pragma unroll
    for (int i = 0; i < 2; i++)
        v[i] = *(const float4*)(a_base + (size_t)(arow + i * 32) * K_DIM + apc * 4);

    CP_WAIT(0);
    __syncthreads();                      // W image + bias visible

    // STS chunk 0 -> buf 0
#pragma unroll
    for (int i = 0; i < 2; i++) {
        __half2 h0 = __float22half2_rn(make_float2(v[i].x, v[i].y));
        __half2 h1 = __float22half2_rn(make_float2(v[i].z, v[i].w));
        uint2 pk; pk.x = *(uint32_t*)&h0; pk.y = *(uint32_t*)&h1;
        *(uint2*)(abufw + (arow + i * 32) * F16_ROW_W + apc * 2) = pk;
    }
    __syncthreads();

    // LDSM per-lane base (halves): row = warpM + (lane&7) + ((lane>>3)&1)*8,
    // +8 halves for lanes 16-31 (second k8-half of the k16 step)
    const uint32_t a_lane_h =
        (uint32_t)((warpM + (lane & 7) + ((lane >> 3) & 1) * 8) * (F16_ROW_W * 2)
                   + (lane >> 4) * 8);
    const uint32_t f16_base = sm_base + OFF_A * 4u;

#pragma unroll
    for (int kc = 0; kc < NCHUNK; kc++) {
        const int par = kc & 1;

        // LDG next chunk (covered by MMA block below)
        if (kc < NCHUNK - 1) {
#pragma unroll
            for (int i = 0; i < 2; i++)
                v[i] = *(const float4*)(a_base + (size_t)(arow + i * 32) * K_DIM
                                        + (kc + 1) * K_CHUNK + apc * 4);
        }

        // ---- MMA phase on buf[par] ----
        // B frags: float4 index = kc*512 + (4*wn + ks)*32 + lane ; second group +64
        const float4* bW = (const float4*)(smem + OFF_W) + kc * 512 + wn * 128 + lane;
        const uint32_t aL = f16_base + (uint32_t)(par * F16_BUF_WORDS) * 4u + a_lane_h * 2u;

        uint32_t afr[2][2][4];            // [ks][mt][4]
#pragma unroll
        for (int mt = 0; mt < 2; mt++)
            ldsm_x4(afr[0][mt][0], afr[0][mt][1], afr[0][mt][2], afr[0][mt][3],
                    aL + (uint32_t)(mt * 16 * F16_ROW_W * 4));

#pragma unroll
        for (int ks = 0; ks < 2; ks++) {
            float4 f0 = bW[ks * 32];          // p = 2*wn
            float4 f1 = bW[ks * 32 + 64];     // p = 2*wn + 1

            if (ks == 0) {
#pragma unroll
                for (int mt = 0; mt < 2; mt++)
                    ldsm_x4(afr[1][mt][0], afr[1][mt][1], afr[1][mt][2], afr[1][mt][3],
                            aL + (uint32_t)(mt * 16 * F16_ROW_W * 4 + 16 * 2));
            }

            uint32_t b0e = __float_as_uint(f0.x), b1e = __float_as_uint(f0.y);
            uint32_t b0o = __float_as_uint(f0.z), b1o = __float_as_uint(f0.w);
            uint32_t c0e = __float_as_uint(f1.x), c1e = __float_as_uint(f1.y);
            uint32_t c0o = __float_as_uint(f1.z), c1o = __float_as_uint(f1.w);
#pragma unroll
            for (int mt = 0; mt < 2; mt++) {
                mma_f16(acc[mt][0], afr[ks][mt], b0e, b1e);
                mma_f16(acc[mt][1], afr[ks][mt], b0o, b1o);
                mma_f16(acc[mt][2], afr[ks][mt], c0e, c1e);
                mma_f16(acc[mt][3], afr[ks][mt], c0o, c1o);
            }
        }

        // ---- cvt + STS next chunk into opposite buffer; single barrier ----
        if (kc < NCHUNK - 1) {
            const int npar = par ^ 1;
#pragma unroll
            for (int i = 0; i < 2; i++) {
                __half2 h0 = __float22half2_rn(make_float2(v[i].x, v[i].y));
                __half2 h1 = __float22half2_rn(make_float2(v[i].z, v[i].w));
                uint2 pk; pk.x = *(uint32_t*)&h0; pk.y = *(uint32_t*)&h1;
                *(uint2*)(abufw + npar * F16_BUF_WORDS
                          + (arow + i * 32) * F16_ROW_W + apc * 2) = pk;
            }
            __syncthreads();
        }
    }

    // ---- epilogue: accum + bias -> gmem (float2, full 32B sectors) ----
    const float* sB = smem + OFF_BIAS;
    const int r0 = warpM + (lane >> 2);
    const int n0 = wn * 32 + (lane & 3) * 2;
#pragma unroll
    for (int mt = 0; mt < 2; mt++) {
#pragma unroll
        for (int hh = 0; hh < 2; hh++) {
            int row = r0 + mt * 16 + hh * 8;
            float* orow = o_base + (size_t)row * N_DIM;
#pragma unroll
            for (int nt = 0; nt < 4; nt++) {
                int n = n0 + nt * 8;
                float2 vv;
                vv.x = acc[mt][nt][hh * 2 + 0] + sB[n];
                vv.y = acc[mt][nt][hh * 2 + 1] + sB[n + 1];
                *(float2*)(orow + n) = vv;
            }
        }
    }
}

// ===================== launch =====================
extern "C" void kernel_launch(void* const* d_in, const int* in_sizes, int n_in,
                              void* d_out, int out_size) {
    const float* x = (const float*)d_in[0];
    const float* W = (const float*)d_in[1];
    const float* b = (const float*)d_in[2];
    float* out = (float*)d_out;

    cudaFuncSetAttribute(gemm_kernel, cudaFuncAttributeMaxDynamicSharedMemorySize, SMEM_BYTES);

    prep_w_kernel<<<512, 256>>>(W);
    gemm_kernel<<<NUM_CTAS, THREADS, SMEM_BYTES>>>(x, b, out);
}